// round 13
// baseline (speedup 1.0000x reference)
#include <cuda_runtime.h>

// ProteinCRF: batched linear-chain CRF NLL.  B=2048, L=2048, T=8.
// out: scalar f32 = mean(denom - num)
//
// R13: eliminate the inter-lane dependency entirely.
//  AUX   : tags -> len, tag-path numerator, nibble-packed tags (R12, proven).
//  SORT  : counting sort of batches by length (1 block). Value-deterministic.
//  SCAN  : 1 THREAD PER BATCH (no shuffles in the recurrence!). 64 blocks x
//          32 thr; warp = 32 length-sorted batches. Per step: 32 fma.rn.f32x2
//          + 8 MUFU + 2 conflict-free LDS from a double-buffered smem tile.
//          Clean main loop (no predication, lengths sorted), short act tail.
//          Per-thread renorm each 8-step chunk. Tags/tiles prefetched 1 ahead.

#define CRF_B 2048
#define CRF_L 2048
#define CRF_T 8
#define SCAN_BLOCKS 64

__device__ float        g_llh[CRF_B];
__device__ float        g_numpart[CRF_B];
__device__ int          g_len[CRF_B];
__device__ int          g_perm[CRF_B];
__device__ unsigned     g_ptags[CRF_B * (CRF_L / 8)];
__device__ unsigned int g_count = 0;

#define PACK2(out, lo, hi) \
    asm("mov.b64 %0, {%1, %2};" : "=l"(out) : "f"(lo), "f"(hi))
#define UNPACK2(lo, hi, in) \
    asm("mov.b64 {%0, %1}, %2;" : "=f"(lo), "=f"(hi) : "l"(in))
#define FMA2(d, a, b, c) \
    asm("fma.rn.f32x2 %0, %1, %2, %3;" : "=l"(d) : "l"(a), "l"(b), "l"(c))
#define MUL2(d, a, b) \
    asm("mul.rn.f32x2 %0, %1, %2;" : "=l"(d) : "l"(a), "l"(b))

// ===================== AUX: tags -> len, numpart, packed ====================
__global__ __launch_bounds__(256)
void crf_aux_kernel(const int* __restrict__ tagsw,
                    const float* __restrict__ transitions,
                    const float* __restrict__ start_tr,
                    const float* __restrict__ end_tr)
{
    __shared__ float s_trans[64];
    __shared__ float s_start[8];
    __shared__ float s_end[8];
    __shared__ float s_sum[8];
    __shared__ int   s_cnt[8];

    const int tid  = threadIdx.x;
    const int lane = tid & 31;
    const int wid  = tid >> 5;
    if (tid < 64) s_trans[tid] = transitions[tid];
    if (tid < 8)  { s_start[tid] = start_tr[tid]; s_end[tid] = end_tr[tid]; }
    __syncthreads();

    const int tstride = (tagsw[1] == 0) ? 2 : 1;   // int64 vs int32 tags
    const int batch   = blockIdx.x;
    const int* tg     = tagsw + (size_t)batch * CRF_L * tstride;

    int lt[8];
    if (tstride == 2) {
        const int4* p = (const int4*)(tg + tid * 16);
        int4 a = p[0], b = p[1], c = p[2], d = p[3];
        lt[0] = a.x; lt[1] = a.z; lt[2] = b.x; lt[3] = b.z;
        lt[4] = c.x; lt[5] = c.z; lt[6] = d.x; lt[7] = d.z;
    } else {
        const int4* p = (const int4*)(tg + tid * 8);
        int4 a = p[0], b = p[1];
        lt[0] = a.x; lt[1] = a.y; lt[2] = a.z; lt[3] = a.w;
        lt[4] = b.x; lt[5] = b.y; lt[6] = b.z; lt[7] = b.w;
    }

    unsigned w = 0;
#pragma unroll
    for (int i = 0; i < 8; i++) w |= (unsigned)(lt[i] & 15) << (4 * i);
    g_ptags[batch * (CRF_L / 8) + tid] = w;

    int prev = (tid == 0) ? 0 : tg[(tid * 8 - 1) * tstride];
    float s  = 0.0f;
    int  cnt = 0;
#pragma unroll
    for (int i = 0; i < 8; i++) {
        if (lt[i] != 0) {
            cnt++;
            s += (tid == 0 && i == 0) ? s_start[lt[0] - 1]
                                      : s_trans[(prev - 1) * 8 + (lt[i] - 1)];
        }
        prev = lt[i];
    }

#pragma unroll
    for (int off = 16; off > 0; off >>= 1) {
        s   += __shfl_xor_sync(0xFFFFFFFFu, s, off);
        cnt += __shfl_xor_sync(0xFFFFFFFFu, cnt, off);
    }
    if (lane == 0) { s_sum[wid] = s; s_cnt[wid] = cnt; }
    __syncthreads();
    if (tid == 0) {
        float tot = 0.0f; int len = 0;
#pragma unroll
        for (int i = 0; i < 8; i++) { tot += s_sum[i]; len += s_cnt[i]; }
        const int last = tg[(len - 1) * tstride] - 1;
        g_numpart[batch] = tot + s_end[last];
        g_len[batch]     = len;
    }
}

// ===================== SORT: counting sort by length =======================
__global__ __launch_bounds__(1024)
void crf_sort_kernel()
{
    __shared__ int s_hist[CRF_L + 1];
    __shared__ int s_off[CRF_L + 1];
    const int tid = threadIdx.x;
    for (int i = tid; i <= CRF_L; i += 1024) s_hist[i] = 0;
    __syncthreads();
    const int l0 = g_len[tid], l1 = g_len[tid + 1024];
    atomicAdd(&s_hist[l0], 1);
    atomicAdd(&s_hist[l1], 1);
    __syncthreads();
    if (tid == 0) {
        int acc = 0;
        for (int i = 0; i <= CRF_L; i++) { s_off[i] = acc; acc += s_hist[i]; }
    }
    __syncthreads();
    int p0 = atomicAdd(&s_off[l0], 1); g_perm[p0] = tid;
    int p1 = atomicAdd(&s_off[l1], 1); g_perm[p1] = tid + 1024;
}

// ===================== SCAN: 1 thread per batch ============================
__device__ __forceinline__ float sel8f(const float* e, int c) {
    int cc = c & 7;
    float s01 = (cc & 1) ? e[1] : e[0];
    float s23 = (cc & 1) ? e[3] : e[2];
    float s45 = (cc & 1) ? e[5] : e[4];
    float s67 = (cc & 1) ? e[7] : e[6];
    float s03 = (cc & 2) ? s23 : s01;
    float s47 = (cc & 2) ? s67 : s45;
    return (cc & 4) ? s47 : s03;
}

// One recurrence step from tile (BUF, step S), tag word WC.  ACT: predicate.
#define CRF_STEP(BUF, S, WC, ACT)                                             \
    {                                                                         \
        float4 lo4 = s_tile[BUF][0][S][lane];                                 \
        float4 hi4 = s_tile[BUF][1][S][lane];                                 \
        float e[8] = { lo4.x, lo4.y, lo4.z, lo4.w,                            \
                       hi4.x, hi4.y, hi4.z, hi4.w };                          \
        unsigned long long bb[8], d[4], exp2_[4];                             \
        _Pragma("unroll")                                                     \
        for (int i = 0; i < 8; i++) PACK2(bb[i], b[i], b[i]);                 \
        _Pragma("unroll")                                                     \
        for (int q = 0; q < 4; q++) {                                         \
            MUL2(d[q], bb[0], e2[0][q]);                                      \
            _Pragma("unroll")                                                 \
            for (int i = 1; i < 8; i++) FMA2(d[q], bb[i], e2[i][q], d[q]);    \
        }                                                                     \
        PACK2(exp2_[0], __expf(e[0]), __expf(e[1]));                          \
        PACK2(exp2_[1], __expf(e[2]), __expf(e[3]));                          \
        PACK2(exp2_[2], __expf(e[4]), __expf(e[5]));                         \
        PACK2(exp2_[3], __expf(e[6]), __expf(e[7]));                          \
        _Pragma("unroll")                                                     \
        for (int q = 0; q < 4; q++) MUL2(d[q], d[q], exp2_[q]);               \
        float u[8];                                                           \
        _Pragma("unroll")                                                     \
        for (int q = 0; q < 4; q++) UNPACK2(u[2*q], u[2*q+1], d[q]);          \
        const bool act_ = (ACT);                                              \
        if (S == 7) { /* per-thread renorm, once per chunk (range < 2^100) */ \
            float m = fmaxf(fmaxf(fmaxf(u[0], u[1]), fmaxf(u[2], u[3])),      \
                            fmaxf(fmaxf(u[4], u[5]), fmaxf(u[6], u[7])));     \
            int ee = ((__float_as_int(m) >> 23) & 0xFF) - 127;                \
            float sc = __int_as_float((127 - ee) << 23);                      \
            _Pragma("unroll")                                                 \
            for (int i = 0; i < 8; i++) u[i] *= sc;                           \
            eacc += act_ ? ee : 0;                                            \
        }                                                                     \
        emsum += act_ ? sel8f(e, (int)(((WC) >> (4 * (S))) & 15u) - 1) : 0.f; \
        _Pragma("unroll")                                                     \
        for (int i = 0; i < 8; i++) b[i] = act_ ? u[i] : b[i];                \
    }

__global__ __launch_bounds__(32, 1)
void crf_scan_kernel(const float* __restrict__ emissions,
                     const float* __restrict__ transitions,
                     const float* __restrict__ start_tr,
                     const float* __restrict__ end_tr,
                     float*       __restrict__ out)
{
    __shared__ float4 s_tile[2][2][8][33];   // [buf][half][step][batch(+pad)]
    __shared__ const float4* s_eb[32];
    const int lane = threadIdx.x;

    const int batch = g_perm[blockIdx.x * 32 + lane];
    const float4* em4 = (const float4*)(emissions + (size_t)batch * (CRF_L * CRF_T));
    s_eb[lane] = em4;

    const int   len     = g_len[batch];
    const float numpart = g_numpart[batch];
    const unsigned* ptg = g_ptags + batch * (CRF_L / 8);

    int minw = len, maxw = len;
#pragma unroll
    for (int off = 16; off > 0; off >>= 1) {
        minw = min(minw, __shfl_xor_sync(0xFFFFFFFFu, minw, off));
        maxw = max(maxw, __shfl_xor_sync(0xFFFFFFFFu, maxw, off));
    }
    const int nclean = minw >> 3;            // chunks fully below minw
    const int cmax   = (maxw + 7) >> 3;

    // E2[i][q] = (exp(trans[i][2q]), exp(trans[i][2q+1]))
    unsigned long long e2[8][4];
#pragma unroll
    for (int i = 0; i < 8; i++)
#pragma unroll
        for (int q = 0; q < 4; q++)
            PACK2(e2[i][q], __expf(transitions[i * 8 + 2 * q]),
                            __expf(transitions[i * 8 + 2 * q + 1]));

    float s_st[8], s_en[8];
#pragma unroll
    for (int i = 0; i < 8; i++) { s_st[i] = start_tr[i]; s_en[i] = end_tr[i]; }

    // cooperative tile fill: chunk c -> buffer fb
    const int fb_b = 2 * 0 + (lane >> 4);    // pattern: b = 2i + (lane>>4)
    const int fp   = lane & 15;
    const int fs   = fp >> 1;
    const int fh   = fp & 1;
#define FILL(C, FB)                                                           \
    {                                                                         \
        const int cc_ = min((C), 255);                                        \
        _Pragma("unroll")                                                     \
        for (int i = 0; i < 16; i++) {                                        \
            int bb_ = 2 * i + (lane >> 4);                                    \
            float4 v = s_eb[bb_][cc_ * 16 + fs * 2 + fh];                     \
            s_tile[FB][fh][fs][bb_] = v;                                      \
        }                                                                     \
    }
    (void)fb_b;

    __syncwarp();
    FILL(0, 0)
    __syncwarp();

    // ---- t = 0 init (per-thread, no cross-lane anything) -------------------
    float b[8];
    float m0;
    float emsum;
    int   eacc = 0;
    unsigned wc = ptg[0], wn = ptg[1];
    {
        float4 lo4 = s_tile[0][0][0][lane];
        float4 hi4 = s_tile[0][1][0][lane];
        float e[8] = { lo4.x, lo4.y, lo4.z, lo4.w, hi4.x, hi4.y, hi4.z, hi4.w };
        float a[8];
#pragma unroll
        for (int i = 0; i < 8; i++) a[i] = s_st[i] + e[i];
        m0 = a[0];
#pragma unroll
        for (int i = 1; i < 8; i++) m0 = fmaxf(m0, a[i]);
#pragma unroll
        for (int i = 0; i < 8; i++) b[i] = __expf(a[i] - m0);
        emsum = sel8f(e, (int)(wc & 15u) - 1);
    }

    // prologue: fill chunk1, steps 1..7 of chunk 0 (clean: 7 < minw)
    FILL(1, 1)
#pragma unroll
    for (int s = 1; s < 8; s++) CRF_STEP(0, s, wc, true)
    __syncwarp();
    wc = wn; wn = ptg[min(2, 255)];

    // ---- clean main loop (no predication; lengths sorted) ------------------
    for (int c = 1; c < nclean; c++) {
        const int buf = c & 1;
        FILL(c + 1, buf ^ 1)
#pragma unroll
        for (int s = 0; s < 8; s++) CRF_STEP(buf, s, wc, true)
        __syncwarp();
        wc = wn; wn = ptg[min(c + 2, 255)];
    }

    // ---- predicated tail ----------------------------------------------------
    for (int c = nclean; c < cmax; c++) {
        const int buf = c & 1;
        FILL(c + 1, buf ^ 1)
        const int t0 = c * 8;
#pragma unroll
        for (int s = 0; s < 8; s++) CRF_STEP(buf, s, wc, (t0 + s) < len)
        __syncwarp();
        wc = wn; wn = ptg[min(c + 2, 255)];
    }

    // ---- finish (per-thread) ------------------------------------------------
    float w = 0.0f;
#pragma unroll
    for (int i = 0; i < 8; i++) w = fmaf(b[i], __expf(s_en[i]), w);
    float denom = m0 + (float)eacc * 0.693147180559945309f + __logf(w);
    g_llh[batch] = denom - (numpart + emsum);

    // ---- last-block-arrives final mean (deterministic) ----------------------
    __threadfence();
    __syncwarp();
    unsigned lastflag = 0;
    if (lane == 0) {
        unsigned old = atomicAdd(&g_count, 1u);
        lastflag = (old == (unsigned)(SCAN_BLOCKS - 1));
    }
    lastflag = __shfl_sync(0xFFFFFFFFu, lastflag, 0);
    if (lastflag) {
        double s = 0.0;
        for (int i = lane; i < CRF_B; i += 32) s += (double)__ldcg(&g_llh[i]);
#pragma unroll
        for (int off = 16; off > 0; off >>= 1)
            s += __shfl_xor_sync(0xFFFFFFFFu, s, off);
        if (lane == 0) {
            out[0] = (float)(s / (double)CRF_B);
            g_count = 0;   // reset for graph replay
        }
    }
}

extern "C" void kernel_launch(void* const* d_in, const int* in_sizes, int n_in,
                              void* d_out, int out_size)
{
    const float* emissions   = (const float*)d_in[0];
    const float* transitions = (const float*)d_in[1];
    const float* start_tr    = (const float*)d_in[2];
    const float* end_tr      = (const float*)d_in[3];
    const int*   tagsw       = (const int*)d_in[4];

    crf_aux_kernel<<<CRF_B, 256>>>(tagsw, transitions, start_tr, end_tr);
    crf_sort_kernel<<<1, 1024>>>();
    crf_scan_kernel<<<SCAN_BLOCKS, 32>>>(
        emissions, transitions, start_tr, end_tr, (float*)d_out);
}

// round 14
// speedup vs baseline: 9.4400x; 9.4400x over previous
#include <cuda_runtime.h>

// ProteinCRF: batched linear-chain CRF NLL.  B=2048, L=2048, T=8.
// out: scalar f32 = mean(denom - num)
//
// R14 = R13's 1-thread-per-batch scan, rebuilt without its two killers:
//   * staging: cp.async (LDGSTS) global->smem, ring of 3 chunks, 2 in flight.
//     No register staging buffers, no smem pointer table, no dependent gathers.
//   * consumption: each lane reads ONLY its own staged rows (2 LDS.128/step,
//     <=4-way conflicts). No cross-lane smem traffic, no syncwarp in the loop.
//   * dot: fma.rn.f32x2 (32 FMA2/step for 8x8 matvec), per-thread renorm.
//   * AUX kernel (R12, measured 9.8us): len, tag-path numerator, packed tags.
//   * clean main loop to warp-min length, predicated tail to warp-max.
//   * deterministic last-block-arrives mean; counter reset for graph replay.

#define CRF_B 2048
#define CRF_L 2048
#define CRF_T 8
#define SCAN_BLOCKS 64
#define NCHUNK      256                    // CRF_L / 8
#define STEP_F      12                     // floats per (step,lane): 8 + 4 pad
#define STEP_STRIDE (32 * STEP_F)          // 384 floats per step plane
#define RING_STRIDE (8 * STEP_STRIDE)      // 3072 floats per ring chunk

__device__ float        g_llh[CRF_B];
__device__ float        g_numpart[CRF_B];
__device__ int          g_len[CRF_B];
__device__ unsigned     g_ptags[CRF_B * NCHUNK];
__device__ unsigned int g_count = 0;

#define PACK2(out, lo, hi) \
    asm("mov.b64 %0, {%1, %2};" : "=l"(out) : "f"(lo), "f"(hi))
#define UNPACK2(lo, hi, in) \
    asm("mov.b64 {%0, %1}, %2;" : "=f"(lo), "=f"(hi) : "l"(in))
#define FMA2(d, a, b, c) \
    asm("fma.rn.f32x2 %0, %1, %2, %3;" : "=l"(d) : "l"(a), "l"(b), "l"(c))
#define MUL2(d, a, b) \
    asm("mul.rn.f32x2 %0, %1, %2;" : "=l"(d) : "l"(a), "l"(b))

__device__ __forceinline__ float ex2f(float x) {
    float r; asm("ex2.approx.f32 %0, %1;" : "=f"(r) : "f"(x)); return r;
}
#define LOG2E 1.44269504088896340736f

// ===================== AUX: tags -> len, numpart, packed (R12) ==============
__global__ __launch_bounds__(256)
void crf_aux_kernel(const int* __restrict__ tagsw,
                    const float* __restrict__ transitions,
                    const float* __restrict__ start_tr,
                    const float* __restrict__ end_tr)
{
    __shared__ float s_trans[64];
    __shared__ float s_start[8];
    __shared__ float s_end[8];
    __shared__ float s_sum[8];
    __shared__ int   s_cnt[8];

    const int tid  = threadIdx.x;
    const int lane = tid & 31;
    const int wid  = tid >> 5;
    if (tid < 64) s_trans[tid] = transitions[tid];
    if (tid < 8)  { s_start[tid] = start_tr[tid]; s_end[tid] = end_tr[tid]; }
    __syncthreads();

    const int tstride = (tagsw[1] == 0) ? 2 : 1;   // int64 vs int32 tags
    const int batch   = blockIdx.x;
    const int* tg     = tagsw + (size_t)batch * CRF_L * tstride;

    int lt[8];
    if (tstride == 2) {
        const int4* p = (const int4*)(tg + tid * 16);
        int4 a = p[0], b = p[1], c = p[2], d = p[3];
        lt[0] = a.x; lt[1] = a.z; lt[2] = b.x; lt[3] = b.z;
        lt[4] = c.x; lt[5] = c.z; lt[6] = d.x; lt[7] = d.z;
    } else {
        const int4* p = (const int4*)(tg + tid * 8);
        int4 a = p[0], b = p[1];
        lt[0] = a.x; lt[1] = a.y; lt[2] = a.z; lt[3] = a.w;
        lt[4] = b.x; lt[5] = b.y; lt[6] = b.z; lt[7] = b.w;
    }

    unsigned w = 0;
#pragma unroll
    for (int i = 0; i < 8; i++) w |= (unsigned)(lt[i] & 15) << (4 * i);
    g_ptags[batch * NCHUNK + tid] = w;

    int prev = (tid == 0) ? 0 : tg[(tid * 8 - 1) * tstride];
    float s  = 0.0f;
    int  cnt = 0;
#pragma unroll
    for (int i = 0; i < 8; i++) {
        if (lt[i] != 0) {
            cnt++;
            s += (tid == 0 && i == 0) ? s_start[lt[0] - 1]
                                      : s_trans[(prev - 1) * 8 + (lt[i] - 1)];
        }
        prev = lt[i];
    }

#pragma unroll
    for (int off = 16; off > 0; off >>= 1) {
        s   += __shfl_xor_sync(0xFFFFFFFFu, s, off);
        cnt += __shfl_xor_sync(0xFFFFFFFFu, cnt, off);
    }
    if (lane == 0) { s_sum[wid] = s; s_cnt[wid] = cnt; }
    __syncthreads();
    if (tid == 0) {
        float tot = 0.0f; int len = 0;
#pragma unroll
        for (int i = 0; i < 8; i++) { tot += s_sum[i]; len += s_cnt[i]; }
        const int last = tg[(len - 1) * tstride] - 1;
        g_numpart[batch] = tot + s_end[last];
        g_len[batch]     = len;
    }
}

// ===================== SCAN: 1 thread per batch, cp.async staged ============
__device__ __forceinline__ float sel8(float4 lo, float4 hi, int c) {
    int cc = c & 7;
    float s01 = (cc & 1) ? lo.y : lo.x;
    float s23 = (cc & 1) ? lo.w : lo.z;
    float s45 = (cc & 1) ? hi.y : hi.x;
    float s67 = (cc & 1) ? hi.w : hi.z;
    float s03 = (cc & 2) ? s23 : s01;
    float s47 = (cc & 2) ? s67 : s45;
    return (cc & 4) ? s47 : s03;
}

#define CPASYNC16(dst_u32, src_ptr) \
    asm volatile("cp.async.cg.shared.global [%0], [%1], 16;" \
                 :: "r"(dst_u32), "l"(src_ptr) : "memory")
#define CP_COMMIT()  asm volatile("cp.async.commit_group;" ::: "memory")
#define CP_WAIT1()   asm volatile("cp.async.wait_group 1;" ::: "memory")
#define CP_WAIT0()   asm volatile("cp.async.wait_group 0;" ::: "memory")

// stage chunk C (8 steps x 32B from my row) into ring slot RG
#define FILL(C, RG) { \
    const int cc_ = min((C), NCHUNK - 1); \
    const float* gsrc_ = em_row + cc_ * 64; \
    const unsigned d0_ = myrow_s + (RG) * (RING_STRIDE * 4); \
    _Pragma("unroll") \
    for (int s2 = 0; s2 < 8; s2++) { \
        CPASYNC16(d0_ + s2 * (STEP_STRIDE * 4),      gsrc_ + s2 * 8); \
        CPASYNC16(d0_ + s2 * (STEP_STRIDE * 4) + 16, gsrc_ + s2 * 8 + 4); \
    } \
    CP_COMMIT(); \
}

// one recurrence step; ACT may be a compile-time literal (clean loop)
#define CRF_STEP(RGOFF, S, WC, ACT) { \
    const float* rp_ = myrow + (RGOFF) + (S) * STEP_STRIDE; \
    float4 lo = *(const float4*)rp_; \
    float4 hi = *(const float4*)(rp_ + 4); \
    unsigned long long p0, p1, p2, p3; \
    PACK2(p0, lo.x, lo.y); PACK2(p1, lo.z, lo.w); \
    PACK2(p2, hi.x, hi.y); PACK2(p3, hi.z, hi.w); \
    MUL2(p0, p0, LOG2E2); MUL2(p1, p1, LOG2E2); \
    MUL2(p2, p2, LOG2E2); MUL2(p3, p3, LOG2E2); \
    float x0,x1,x2,x3,x4,x5,x6,x7; \
    UNPACK2(x0,x1,p0); UNPACK2(x2,x3,p1); \
    UNPACK2(x4,x5,p2); UNPACK2(x6,x7,p3); \
    PACK2(p0, ex2f(x0), ex2f(x1)); PACK2(p1, ex2f(x2), ex2f(x3)); \
    PACK2(p2, ex2f(x4), ex2f(x5)); PACK2(p3, ex2f(x6), ex2f(x7)); \
    unsigned long long a0_, a1_, a2_, a3_, bbp; \
    PACK2(bbp, b[0], b[0]); \
    MUL2(a0_, bbp, e2[0][0]); MUL2(a1_, bbp, e2[0][1]); \
    MUL2(a2_, bbp, e2[0][2]); MUL2(a3_, bbp, e2[0][3]); \
    _Pragma("unroll") \
    for (int i = 1; i < 8; i++) { \
        PACK2(bbp, b[i], b[i]); \
        FMA2(a0_, bbp, e2[i][0], a0_); FMA2(a1_, bbp, e2[i][1], a1_); \
        FMA2(a2_, bbp, e2[i][2], a2_); FMA2(a3_, bbp, e2[i][3], a3_); \
    } \
    MUL2(a0_, a0_, p0); MUL2(a1_, a1_, p1); \
    MUL2(a2_, a2_, p2); MUL2(a3_, a3_, p3); \
    float u[8]; \
    UNPACK2(u[0],u[1],a0_); UNPACK2(u[2],u[3],a1_); \
    UNPACK2(u[4],u[5],a2_); UNPACK2(u[6],u[7],a3_); \
    const bool act_ = (ACT); \
    if ((S) == 7) { /* per-thread renorm once per chunk; range < 2^100 */ \
        float m_ = fmaxf(fmaxf(fmaxf(u[0],u[1]), fmaxf(u[2],u[3])), \
                         fmaxf(fmaxf(u[4],u[5]), fmaxf(u[6],u[7]))); \
        int ee_ = ((__float_as_int(m_) >> 23) & 0xFF) - 127; \
        float sc_ = __int_as_float((127 - ee_) << 23); \
        _Pragma("unroll") \
        for (int i = 0; i < 8; i++) u[i] *= sc_; \
        eacc += act_ ? ee_ : 0; \
    } \
    emsum += act_ ? sel8(lo, hi, (int)(((WC) >> (4 * (S))) & 15u) - 1) : 0.0f; \
    _Pragma("unroll") \
    for (int i = 0; i < 8; i++) b[i] = act_ ? u[i] : b[i]; \
}

__global__ __launch_bounds__(32, 1)
void crf_scan_kernel(const float* __restrict__ emissions,
                     const float* __restrict__ transitions,
                     const float* __restrict__ start_tr,
                     const float* __restrict__ end_tr,
                     float*       __restrict__ out)
{
    __shared__ float s_em[3 * RING_STRIDE];   // 36 KB ring

    const int lane  = threadIdx.x;
    const int batch = blockIdx.x * 32 + lane;

    const float* em_row = emissions + (size_t)batch * (CRF_L * CRF_T);
    float*   myrow   = s_em + lane * STEP_F;
    const unsigned myrow_s = (unsigned)__cvta_generic_to_shared(myrow);

    const int   len     = g_len[batch];
    const float numpart = g_numpart[batch];
    const unsigned* ptg = g_ptags + batch * NCHUNK;

    int minw = len, maxw = len;
#pragma unroll
    for (int off = 16; off > 0; off >>= 1) {
        minw = min(minw, __shfl_xor_sync(0xFFFFFFFFu, minw, off));
        maxw = max(maxw, __shfl_xor_sync(0xFFFFFFFFu, maxw, off));
    }
    const int nclean = (minw - 7) >> 3;   // chunks [0, nclean) fully active
    const int cmax   = (maxw + 7) >> 3;

    // start the pipeline before the (L2) setup loads below
    FILL(0, 0)
    FILL(1, 1)

    unsigned long long LOG2E2;
    PACK2(LOG2E2, LOG2E, LOG2E);

    // E2[i][q] = (exp(trans[i][2q]), exp(trans[i][2q+1]))  -- 64 f32 regs
    unsigned long long e2[8][4];
#pragma unroll
    for (int i = 0; i < 8; i++)
#pragma unroll
        for (int q = 0; q < 4; q++)
            PACK2(e2[i][q], __expf(transitions[i * 8 + 2 * q]),
                            __expf(transitions[i * 8 + 2 * q + 1]));

    float st[8], en[8];
#pragma unroll
    for (int i = 0; i < 8; i++) { st[i] = start_tr[i]; en[i] = end_tr[i]; }

    unsigned wc = ptg[0], wn = ptg[1];

    float b[8];
    float m0, emsum;
    int   eacc = 0;

    // ---- chunk 0: wait, keep pipeline primed, init t=0, steps 1..7 ---------
    CP_WAIT1();
    FILL(2, 2)
    {
        float4 lo = *(const float4*)myrow;
        float4 hi = *(const float4*)(myrow + 4);
        float a[8] = { st[0] + lo.x, st[1] + lo.y, st[2] + lo.z, st[3] + lo.w,
                       st[4] + hi.x, st[5] + hi.y, st[6] + hi.z, st[7] + hi.w };
        m0 = a[0];
#pragma unroll
        for (int i = 1; i < 8; i++) m0 = fmaxf(m0, a[i]);
#pragma unroll
        for (int i = 0; i < 8; i++) b[i] = ex2f((a[i] - m0) * LOG2E);
        emsum = sel8(lo, hi, (int)(wc & 15u) - 1);
    }
#pragma unroll
    for (int s = 1; s < 8; s++) CRF_STEP(0, s, wc, true)
    wc = wn; wn = ptg[2];

    // ---- clean main loop (all lanes active; minw >= 1024 >> 8) -------------
    for (int c = 1; c < nclean; c++) {
        const int rgoff = (c % 3) * RING_STRIDE;
        CP_WAIT1();
        FILL(c + 2, (c + 2) % 3)
#pragma unroll
        for (int s = 0; s < 8; s++) CRF_STEP(rgoff, s, wc, true)
        wc = wn; wn = ptg[min(c + 2, NCHUNK - 1)];
    }

    // ---- predicated tail ----------------------------------------------------
    for (int c = nclean; c < cmax; c++) {
        const int rgoff = (c % 3) * RING_STRIDE;
        CP_WAIT1();
        FILL(c + 2, (c + 2) % 3)
        const int t0 = c * 8;
#pragma unroll
        for (int s = 0; s < 8; s++) CRF_STEP(rgoff, s, wc, (t0 + s) < len)
        wc = wn; wn = ptg[min(c + 2, NCHUNK - 1)];
    }
    CP_WAIT0();

    // ---- finish (per-thread) ------------------------------------------------
    float w = 0.0f;
#pragma unroll
    for (int i = 0; i < 8; i++) w = fmaf(b[i], __expf(en[i]), w);
    float denom = m0 + (float)eacc * 0.693147180559945309f + __logf(w);
    g_llh[batch] = denom - (numpart + emsum);

    // ---- last-block-arrives final mean (deterministic) ----------------------
    __threadfence();
    __syncwarp();
    unsigned lastflag = 0;
    if (lane == 0) {
        unsigned old = atomicAdd(&g_count, 1u);
        lastflag = (old == (unsigned)(SCAN_BLOCKS - 1));
    }
    lastflag = __shfl_sync(0xFFFFFFFFu, lastflag, 0);
    if (lastflag) {
        double s = 0.0;
        for (int i = lane; i < CRF_B; i += 32) s += (double)__ldcg(&g_llh[i]);
#pragma unroll
        for (int off = 16; off > 0; off >>= 1)
            s += __shfl_xor_sync(0xFFFFFFFFu, s, off);
        if (lane == 0) {
            out[0] = (float)(s / (double)CRF_B);
            g_count = 0;   // reset for graph replay
        }
    }
}

extern "C" void kernel_launch(void* const* d_in, const int* in_sizes, int n_in,
                              void* d_out, int out_size)
{
    const float* emissions   = (const float*)d_in[0];
    const float* transitions = (const float*)d_in[1];
    const float* start_tr    = (const float*)d_in[2];
    const float* end_tr      = (const float*)d_in[3];
    const int*   tagsw       = (const int*)d_in[4];

    crf_aux_kernel<<<CRF_B, 256>>>(tagsw, transitions, start_tr, end_tr);
    crf_scan_kernel<<<SCAN_BLOCKS, 32>>>(
        emissions, transitions, start_tr, end_tr, (float*)d_out);
}